// round 4
// baseline (speedup 1.0000x reference)
#include <cuda_runtime.h>
#include <stdint.h>

#define DIM        3200
#define HID        6400
#define NTOK       16384   // 8 * 2048
#define NEW_START  32000

#define MAXM_FAST  64      // fast path covers rows [0, 64)
#define BN         128     // n per block
#define BKT        32      // k per smem stage
#define SPLITS1    10      // layer1: K=3200 -> 320 per split
#define KCH1       320
#define SPLITS2    20      // layer2: K=6400 -> 320 per split
#define KCH2       320

// fallback tiling (old latency-path kernel for rows >= 64)
#define FBM 64
#define FBN 64
#define FBK 16
#define FTM 4
#define FTN 4

// ---------------- scratch (static device globals; no allocation) ----------------
__device__ int   g_count;
__device__ int   g_tok[NTOK];
__device__ float g_H[(size_t)NTOK * HID];                        // hidden activations
__device__ float g_P[(size_t)SPLITS2 * MAXM_FAST * HID];         // split-K partials

// ---------------- f32x2 helpers ----------------
__device__ __forceinline__ unsigned long long pack2(float lo, float hi) {
    unsigned long long r;
    asm("mov.b64 %0, {%1, %2};" : "=l"(r) : "f"(lo), "f"(hi));
    return r;
}
__device__ __forceinline__ void unpk2(unsigned long long v, float& lo, float& hi) {
    asm("mov.b64 {%0, %1}, %2;" : "=f"(lo), "=f"(hi) : "l"(v));
}
__device__ __forceinline__ void fma2(unsigned long long& d, unsigned long long a,
                                     unsigned long long b) {
    asm("fma.rn.f32x2 %0, %1, %2, %0;" : "+l"(d) : "l"(a), "l"(b));
}

// ---------------- kernel 0/1: reset + compact ----------------
__global__ void k_reset() { g_count = 0; }

__global__ void k_compact(const int* __restrict__ ids) {
    int t = blockIdx.x * blockDim.x + threadIdx.x;
    if (t < NTOK && ids[t] >= NEW_START) {
        int p = atomicAdd(&g_count, 1);
        g_tok[p] = t;
    }
}

// ---------------- kernel 2: embedding copy (all tokens) ----------------
__global__ void k_copy(const float* __restrict__ emb,
                       const int*   __restrict__ ids,
                       float*       __restrict__ out) {
    int t = blockIdx.x;
    const float4* src = (const float4*)(emb + (size_t)ids[t] * DIM);
    float4*       dst = (float4*)(out + (size_t)t * DIM);
    #pragma unroll 4
    for (int i = threadIdx.x; i < DIM / 4; i += blockDim.x)
        dst[i] = src[i];
}

// ---------------- fast split-K GEMM (rows [0,64), f32x2 inner loop) ----------------
// grid: (N/BN, splits). Each block: 64 m x 128 n, K-chunk kchunk.
// Writes partials to g_P[(split*64 + m)*N + n].
// GATHER_A=1: A row m = A + g_tok[m]*lda ; GATHER_A=0: A row m = g_H + m*lda
template<int GATHER_A>
__global__ void __launch_bounds__(256, 3)
k_gs(const float* __restrict__ A,
     const float* __restrict__ B,     // weights [K, N] row-major
     int N, int kchunk, int lda) {
    __shared__ float As[2][BKT][MAXM_FAST];   // 16 KB

    const int count = g_count;
    const int n0 = blockIdx.x * BN;
    const int kbase = blockIdx.y * kchunk;
    const int nstage = kchunk / BKT;

    const int tid = threadIdx.x;     // 256
    const int tx = tid & 63;         // n-pair index: n = n0 + 2*tx
    const int ty = tid >> 6;         // 0..3 : m-group of 16

    // A staging assignment: thread loads row s_m, k-offsets s_kg*4 and s_kg*4+16
    const int s_m  = tid & 63;
    const int s_kg = tid >> 6;       // 0..3
    const float* arow = nullptr;
    if (s_m < count) {
        if (GATHER_A) arow = A   + (size_t)g_tok[s_m] * lda;
        else          arow = g_H + (size_t)s_m        * lda;
    }

    // accumulators: 8 m-pairs x 2 n, packed f32x2 over the m-pair
    unsigned long long acc[8][2];
    #pragma unroll
    for (int p = 0; p < 8; p++) { acc[p][0] = 0ull; acc[p][1] = 0ull; }

    // prefetch regs for A stage
    float4 pa, pb;

    // load stage 0 into buffer 0
    {
        pa = make_float4(0.f, 0.f, 0.f, 0.f);
        pb = pa;
        if (arow) {
            pa = *(const float4*)(arow + kbase + s_kg * 4);
            pb = *(const float4*)(arow + kbase + s_kg * 4 + 16);
        }
        #pragma unroll
        for (int j = 0; j < 4; j++) {
            As[0][s_kg * 4 + j][s_m]      = ((const float*)&pa)[j];
            As[0][s_kg * 4 + 16 + j][s_m] = ((const float*)&pb)[j];
        }
    }
    __syncthreads();

    for (int s = 0; s < nstage; s++) {
        const int buf = s & 1;
        // prefetch next stage into registers
        bool has_next = (s + 1) < nstage;
        if (has_next) {
            pa = make_float4(0.f, 0.f, 0.f, 0.f);
            pb = pa;
            if (arow) {
                int ko = kbase + (s + 1) * BKT;
                pa = *(const float4*)(arow + ko + s_kg * 4);
                pb = *(const float4*)(arow + ko + s_kg * 4 + 16);
            }
        }

        // compute current stage: B streamed straight from gmem
        const float* bp = B + (size_t)(kbase + s * BKT) * N + n0 + tx * 2;
        #pragma unroll
        for (int kk = 0; kk < BKT; kk++) {
            float2 bv = *(const float2*)bp;
            bp += N;
            unsigned long long b0 = pack2(bv.x, bv.x);
            unsigned long long b1 = pack2(bv.y, bv.y);
            const ulonglong2* ap = (const ulonglong2*)&As[buf][kk][ty * 16];
            #pragma unroll
            for (int q = 0; q < 4; q++) {
                ulonglong2 av = ap[q];          // 2 m-pairs
                fma2(acc[q * 2 + 0][0], av.x, b0);
                fma2(acc[q * 2 + 0][1], av.x, b1);
                fma2(acc[q * 2 + 1][0], av.y, b0);
                fma2(acc[q * 2 + 1][1], av.y, b1);
            }
        }

        if (has_next) {
            __syncthreads();   // everyone done reading buf before writing buf^1? (write other buf: only needed vs readers of that buf from prev iter)
            #pragma unroll
            for (int j = 0; j < 4; j++) {
                As[buf ^ 1][s_kg * 4 + j][s_m]      = ((const float*)&pa)[j];
                As[buf ^ 1][s_kg * 4 + 16 + j][s_m] = ((const float*)&pb)[j];
            }
            __syncthreads();
        }
    }

    // write partials: unique (split, m, n) writer -> deterministic
    float* pbase = g_P + (size_t)blockIdx.y * MAXM_FAST * N + n0 + tx * 2;
    #pragma unroll
    for (int p = 0; p < 8; p++) {
        float a0, a1, b0, b1;
        unpk2(acc[p][0], a0, a1);
        unpk2(acc[p][1], b0, b1);
        int m = ty * 16 + 2 * p;
        *(float2*)(pbase + (size_t)m * N)       = make_float2(a0, b0);
        *(float2*)(pbase + (size_t)(m + 1) * N) = make_float2(a1, b1);
    }
}

// ---------------- finalize: reduce splits + bias (+relu) + write ----------------
__global__ void k_fin(const float* __restrict__ bias,
                      float*       __restrict__ dst,    // used when scatter==1
                      int N, int splits, int relu, int scatter, int ldc) {
    const int n = blockIdx.x * 256 + threadIdx.x;
    const int m = blockIdx.y;
    const int count = g_count;
    if (n >= N || m >= count) return;
    float s = bias[n];
    for (int i = 0; i < splits; i++)
        s += g_P[((size_t)i * MAXM_FAST + m) * N + n];
    if (relu) s = fmaxf(s, 0.f);
    if (scatter) dst[(size_t)g_tok[m] * ldc + n] = s;
    else         g_H[(size_t)m * ldc + n] = s;
}

// ---------------- fallback full-K GEMM (rows >= 64; early-exits normally) --------
template<int RELU, int GATHER_A, int SCATTER_C>
__global__ void k_gemm(const float* __restrict__ A,
                       const float* __restrict__ B,
                       const float* __restrict__ bias,
                       float*       __restrict__ C,
                       int N, int K, int lda, int ldc) {
    __shared__ float As[FBK][FBM + 1];
    __shared__ float Bs[FBK][FBN];

    const int count = g_count;
    const int m0 = MAXM_FAST + blockIdx.y * FBM;
    if (m0 >= count) return;
    const int n0 = blockIdx.x * FBN;

    const int tid = threadIdx.x;
    const int tx = tid & 15;
    const int ty = tid >> 4;

    const int a_mi = tid >> 2;
    const int a_k  = (tid & 3) * 4;
    const int a_m  = m0 + a_mi;
    const float* arow = nullptr;
    if (a_m < count) {
        if (GATHER_A) arow = A + (size_t)g_tok[a_m] * lda;
        else          arow = g_H + (size_t)a_m * lda;
    }

    const int b_kb = tid >> 4;
    const int b_n  = (tid & 15) * 4;

    float acc[FTM][FTN];
    #pragma unroll
    for (int i = 0; i < FTM; i++)
        #pragma unroll
        for (int j = 0; j < FTN; j++) acc[i][j] = 0.0f;

    for (int k0 = 0; k0 < K; k0 += FBK) {
        float4 va = make_float4(0.f, 0.f, 0.f, 0.f);
        if (arow) va = *(const float4*)(arow + k0 + a_k);
        As[a_k + 0][a_mi] = va.x;
        As[a_k + 1][a_mi] = va.y;
        As[a_k + 2][a_mi] = va.z;
        As[a_k + 3][a_mi] = va.w;

        float4 vb = *(const float4*)(B + (size_t)(k0 + b_kb) * N + n0 + b_n);
        *(float4*)&Bs[b_kb][b_n] = vb;

        __syncthreads();

        #pragma unroll
        for (int kk = 0; kk < FBK; kk++) {
            float a[FTM], b[FTN];
            #pragma unroll
            for (int i = 0; i < FTM; i++) a[i] = As[kk][ty * FTM + i];
            #pragma unroll
            for (int j = 0; j < FTN; j++) b[j] = Bs[kk][tx * FTN + j];
            #pragma unroll
            for (int i = 0; i < FTM; i++)
                #pragma unroll
                for (int j = 0; j < FTN; j++)
                    acc[i][j] = fmaf(a[i], b[j], acc[i][j]);
        }
        __syncthreads();
    }

    const int n = n0 + tx * FTN;
    float4 bv = *(const float4*)(bias + n);
    #pragma unroll
    for (int i = 0; i < FTM; i++) {
        int m = m0 + ty * FTM + i;
        if (m >= count) continue;
        float* crow;
        if (SCATTER_C) crow = C + (size_t)g_tok[m] * ldc;
        else           crow = g_H + (size_t)m * ldc;
        float4 v;
        v.x = acc[i][0] + bv.x;
        v.y = acc[i][1] + bv.y;
        v.z = acc[i][2] + bv.z;
        v.w = acc[i][3] + bv.w;
        if (RELU) {
            v.x = fmaxf(v.x, 0.f);
            v.y = fmaxf(v.y, 0.f);
            v.z = fmaxf(v.z, 0.f);
            v.w = fmaxf(v.w, 0.f);
        }
        *(float4*)(crow + n) = v;
    }
}

// ---------------- launch ----------------
extern "C" void kernel_launch(void* const* d_in, const int* in_sizes, int n_in,
                              void* d_out, int out_size) {
    const int*   ids = (const int*)  d_in[0];
    const float* emb = (const float*)d_in[1];
    const float* w1  = (const float*)d_in[2];
    const float* b1  = (const float*)d_in[3];
    const float* w2  = (const float*)d_in[4];
    const float* b2  = (const float*)d_in[5];
    float*       out = (float*)d_out;

    k_reset<<<1, 1>>>();
    k_compact<<<NTOK / 256, 256>>>(ids);
    k_copy<<<NTOK, 256>>>(emb, ids, out);

    // ===== layer 1: H = relu(out[tok] @ W1 + b1), K=3200 =====
    {
        dim3 gs(HID / BN, SPLITS1);
        k_gs<1><<<gs, 256>>>(out, w1, HID, KCH1, DIM);
        dim3 gf((HID + 255) / 256, MAXM_FAST);
        k_fin<<<gf, 256>>>(b1, nullptr, HID, SPLITS1, 1, 0, HID);
        // fallback for rows >= 64 (early-exits when count <= 64)
        dim3 gb(HID / FBN, (NTOK - MAXM_FAST) / FBM);
        k_gemm<1, 1, 0><<<gb, 256>>>(out, w1, b1, nullptr, HID, DIM, DIM, HID);
    }

    // ===== layer 2: out[tok] = H @ W2 + b2, K=6400 =====
    {
        dim3 gs(DIM / BN, SPLITS2);
        k_gs<0><<<gs, 256>>>(nullptr, w2, DIM, KCH2, HID);
        dim3 gf((DIM + 255) / 256, MAXM_FAST);
        k_fin<<<gf, 256>>>(b2, out, DIM, SPLITS2, 0, 1, DIM);
        dim3 gb(DIM / FBN, (NTOK - MAXM_FAST) / FBM);
        k_gemm<0, 0, 1><<<gb, 256>>>(nullptr, w2, b2, out, DIM, HID, HID, DIM);
    }
}

// round 5
// speedup vs baseline: 1.3312x; 1.3312x over previous
#include <cuda_runtime.h>
#include <stdint.h>

#define DIM        3200
#define HID        6400
#define NTOK       16384   // 8 * 2048
#define NEW_START  32000

#define MAXM       64      // fast path covers rows [0, 64)
#define BN         128     // n per block
#define BK         16      // k per smem stage
#define SPLITS1    20      // layer1: K=3200 -> 160 per split (10 stages)
#define KCH1       160
#define SPLITS2    40      // layer2: K=6400 -> 160 per split (10 stages)
#define KCH2       160

// fallback tiling (rows >= 64; early-exits normally)
#define FBM 64
#define FBN 64
#define FBK 16
#define FTM 4
#define FTN 4

// ---------------- scratch (static device globals; no allocation) ----------------
__device__ int   g_count;
__device__ int   g_tok[NTOK];
__device__ float g_H[(size_t)NTOK * HID];                    // hidden activations
__device__ float g_P[(size_t)SPLITS2 * MAXM * DIM];          // split-K partials (32.8MB)
// layer1 needs SPLITS1*64*HID = 20*64*6400 = 8.192M floats; layer2 = 40*64*3200 = same. OK.

// ---------------- f32x2 helpers ----------------
typedef unsigned long long u64t;
__device__ __forceinline__ u64t pack2(float lo, float hi) {
    u64t r;
    asm("mov.b64 %0, {%1, %2};" : "=l"(r) : "f"(lo), "f"(hi));
    return r;
}
__device__ __forceinline__ void unpk2(u64t v, float& lo, float& hi) {
    asm("mov.b64 {%0, %1}, %2;" : "=f"(lo), "=f"(hi) : "l"(v));
}
__device__ __forceinline__ void fma2(u64t& d, u64t a, u64t b) {
    asm("fma.rn.f32x2 %0, %1, %2, %0;" : "+l"(d) : "l"(a), "l"(b));
}

// ---------------- kernel 0/1: reset + compact ----------------
__global__ void k_reset() { g_count = 0; }

__global__ void k_compact(const int* __restrict__ ids) {
    int t = blockIdx.x * blockDim.x + threadIdx.x;
    if (t < NTOK && ids[t] >= NEW_START) {
        int p = atomicAdd(&g_count, 1);
        g_tok[p] = t;
    }
}

// ---------------- kernel 2: embedding copy (all tokens) ----------------
__global__ void k_copy(const float* __restrict__ emb,
                       const int*   __restrict__ ids,
                       float*       __restrict__ out) {
    int t = blockIdx.x;
    const float4* src = (const float4*)(emb + (size_t)ids[t] * DIM);
    float4*       dst = (float4*)(out + (size_t)t * DIM);
    #pragma unroll 4
    for (int i = threadIdx.x; i < DIM / 4; i += blockDim.x)
        dst[i] = src[i];
}

// ---------------- fast split-K GEMM: 64m x 128n block, 8x8 thread tile, f32x2 ----
// grid: (N/BN, splits), block: 128 threads.
// Thread (tx = tid&15, ty = tid>>4) owns m = ty*8..+8 (4 f32x2 m-pairs),
// n = {tx*4..+4} U {64+tx*4..+4}.
// Writes partials to g_P[(split*64 + m)*N + n]. Unique writer -> deterministic.
// GATHER_A=1: A row m = A + g_tok[m]*lda ; GATHER_A=0: A row m = g_H + m*lda
template<int GATHER_A>
__global__ void __launch_bounds__(128, 4)
k_gs(const float* __restrict__ A,
     const float* __restrict__ B,     // weights [K, N] row-major
     int N, int kchunk, int lda) {
    __shared__ float As[BK][MAXM];    // 4 KB
    __shared__ float Bs[BK][BN];      // 8 KB

    const int count = g_count;
    const int n0 = blockIdx.x * BN;
    const int kbase = blockIdx.y * kchunk;
    const int nstage = kchunk / BK;

    const int tid = threadIdx.x;      // 128
    const int tx = tid & 15;
    const int ty = tid >> 4;          // 0..7

    // A loader: row a_m, k-halves a_kh*8..+8 (2 float4)
    const int a_m  = tid & 63;
    const int a_kh = tid >> 6;        // 0/1
    const float* arow = nullptr;
    if (a_m < count) {
        if (GATHER_A) arow = A   + (size_t)g_tok[a_m] * lda;
        else          arow = g_H + (size_t)a_m        * lda;
    }

    // B loader: row b_k, 16 consecutive n starting at b_n (4 float4)
    const int b_k = tid >> 3;         // 0..15
    const int b_n = (tid & 7) * 16;   // 0..112

    // acc[p][j]: m-pair p (m = ty*8 + 2p, lanes m/m+1), n index j (j<4: tx*4+j, j>=4: 64+tx*4+j-4)
    u64t acc[4][8];
    #pragma unroll
    for (int p = 0; p < 4; p++)
        #pragma unroll
        for (int j = 0; j < 8; j++) acc[p][j] = 0ull;

    for (int s = 0; s < nstage; s++) {
        const int k0 = kbase + s * BK;

        // prefetch this stage into registers (overlaps previous stage's compute)
        float4 av0 = make_float4(0.f, 0.f, 0.f, 0.f), av1 = av0;
        if (arow) {
            av0 = *(const float4*)(arow + k0 + a_kh * 8);
            av1 = *(const float4*)(arow + k0 + a_kh * 8 + 4);
        }
        float4 bv0 = *(const float4*)(B + (size_t)(k0 + b_k) * N + n0 + b_n);
        float4 bv1 = *(const float4*)(B + (size_t)(k0 + b_k) * N + n0 + b_n + 4);
        float4 bv2 = *(const float4*)(B + (size_t)(k0 + b_k) * N + n0 + b_n + 8);
        float4 bv3 = *(const float4*)(B + (size_t)(k0 + b_k) * N + n0 + b_n + 12);

        __syncthreads();   // previous stage's readers done

        #pragma unroll
        for (int j = 0; j < 4; j++) {
            As[a_kh * 8 + j][a_m]     = ((const float*)&av0)[j];
            As[a_kh * 8 + 4 + j][a_m] = ((const float*)&av1)[j];
        }
        *(float4*)&Bs[b_k][b_n]      = bv0;
        *(float4*)&Bs[b_k][b_n + 4]  = bv1;
        *(float4*)&Bs[b_k][b_n + 8]  = bv2;
        *(float4*)&Bs[b_k][b_n + 12] = bv3;

        __syncthreads();   // tiles ready

        #pragma unroll
        for (int kk = 0; kk < BK; kk++) {
            // A: 4 m-pairs (broadcast within half-warp)
            ulonglong2 a01 = *(const ulonglong2*)&As[kk][ty * 8];
            ulonglong2 a23 = *(const ulonglong2*)&As[kk][ty * 8 + 4];
            // B: 8 n values in two 16B chunks 256B apart (conflict-free)
            float4 b0 = *(const float4*)&Bs[kk][tx * 4];
            float4 b1 = *(const float4*)&Bs[kk][64 + tx * 4];
            u64t bd[8];
            bd[0] = pack2(b0.x, b0.x); bd[1] = pack2(b0.y, b0.y);
            bd[2] = pack2(b0.z, b0.z); bd[3] = pack2(b0.w, b0.w);
            bd[4] = pack2(b1.x, b1.x); bd[5] = pack2(b1.y, b1.y);
            bd[6] = pack2(b1.z, b1.z); bd[7] = pack2(b1.w, b1.w);
            u64t ap[4] = {a01.x, a01.y, a23.x, a23.y};
            #pragma unroll
            for (int p = 0; p < 4; p++)
                #pragma unroll
                for (int j = 0; j < 8; j++)
                    fma2(acc[p][j], ap[p], bd[j]);
        }
    }

    // write partials: rows m..m+1 per pair, two float4 groups per row
    float* pbase = g_P + (size_t)blockIdx.y * MAXM * N;
    #pragma unroll
    for (int p = 0; p < 4; p++) {
        int m = ty * 8 + 2 * p;
        float lo[8], hi[8];
        #pragma unroll
        for (int j = 0; j < 8; j++) unpk2(acc[p][j], lo[j], hi[j]);
        float* r0 = pbase + (size_t)m * N + n0;
        float* r1 = pbase + (size_t)(m + 1) * N + n0;
        *(float4*)(r0 + tx * 4)      = make_float4(lo[0], lo[1], lo[2], lo[3]);
        *(float4*)(r0 + 64 + tx * 4) = make_float4(lo[4], lo[5], lo[6], lo[7]);
        *(float4*)(r1 + tx * 4)      = make_float4(hi[0], hi[1], hi[2], hi[3]);
        *(float4*)(r1 + 64 + tx * 4) = make_float4(hi[4], hi[5], hi[6], hi[7]);
    }
}

// ---------------- finalize: reduce splits + bias (+relu) + write ----------------
__global__ void k_fin(const float* __restrict__ bias,
                      float*       __restrict__ dst,    // used when scatter==1
                      int N, int splits, int relu, int scatter, int ldc) {
    const int n = blockIdx.x * 256 + threadIdx.x;
    const int m = blockIdx.y;
    const int count = g_count;
    if (n >= N || m >= count) return;
    float s = bias[n];
    for (int i = 0; i < splits; i++)
        s += g_P[((size_t)i * MAXM + m) * N + n];
    if (relu) s = fmaxf(s, 0.f);
    if (scatter) dst[(size_t)g_tok[m] * ldc + n] = s;
    else         g_H[(size_t)m * ldc + n] = s;
}

// ---------------- fallback full-K GEMM (rows >= 64; early-exits normally) --------
template<int RELU, int GATHER_A, int SCATTER_C>
__global__ void k_gemm(const float* __restrict__ A,
                       const float* __restrict__ B,
                       const float* __restrict__ bias,
                       float*       __restrict__ C,
                       int N, int K, int lda, int ldc) {
    __shared__ float As[FBK][FBM + 1];
    __shared__ float Bs[FBK][FBN];

    const int count = g_count;
    const int m0 = MAXM + blockIdx.y * FBM;
    if (m0 >= count) return;
    const int n0 = blockIdx.x * FBN;

    const int tid = threadIdx.x;
    const int tx = tid & 15;
    const int ty = tid >> 4;

    const int a_mi = tid >> 2;
    const int a_k  = (tid & 3) * 4;
    const int a_m  = m0 + a_mi;
    const float* arow = nullptr;
    if (a_m < count) {
        if (GATHER_A) arow = A + (size_t)g_tok[a_m] * lda;
        else          arow = g_H + (size_t)a_m * lda;
    }

    const int b_kb = tid >> 4;
    const int b_n  = (tid & 15) * 4;

    float acc[FTM][FTN];
    #pragma unroll
    for (int i = 0; i < FTM; i++)
        #pragma unroll
        for (int j = 0; j < FTN; j++) acc[i][j] = 0.0f;

    for (int k0 = 0; k0 < K; k0 += FBK) {
        float4 va = make_float4(0.f, 0.f, 0.f, 0.f);
        if (arow) va = *(const float4*)(arow + k0 + a_k);
        As[a_k + 0][a_mi] = va.x;
        As[a_k + 1][a_mi] = va.y;
        As[a_k + 2][a_mi] = va.z;
        As[a_k + 3][a_mi] = va.w;

        float4 vb = *(const float4*)(B + (size_t)(k0 + b_kb) * N + n0 + b_n);
        *(float4*)&Bs[b_kb][b_n] = vb;

        __syncthreads();

        #pragma unroll
        for (int kk = 0; kk < FBK; kk++) {
            float a[FTM], b[FTN];
            #pragma unroll
            for (int i = 0; i < FTM; i++) a[i] = As[kk][ty * FTM + i];
            #pragma unroll
            for (int j = 0; j < FTN; j++) b[j] = Bs[kk][tx * FTN + j];
            #pragma unroll
            for (int i = 0; i < FTM; i++)
                #pragma unroll
                for (int j = 0; j < FTN; j++)
                    acc[i][j] = fmaf(a[i], b[j], acc[i][j]);
        }
        __syncthreads();
    }

    const int n = n0 + tx * FTN;
    float4 bv = *(const float4*)(bias + n);
    #pragma unroll
    for (int i = 0; i < FTM; i++) {
        int m = m0 + ty * FTM + i;
        if (m >= count) continue;
        float* crow;
        if (SCATTER_C) crow = C + (size_t)g_tok[m] * ldc;
        else           crow = g_H + (size_t)m * ldc;
        float4 v;
        v.x = acc[i][0] + bv.x;
        v.y = acc[i][1] + bv.y;
        v.z = acc[i][2] + bv.z;
        v.w = acc[i][3] + bv.w;
        if (RELU) {
            v.x = fmaxf(v.x, 0.f);
            v.y = fmaxf(v.y, 0.f);
            v.z = fmaxf(v.z, 0.f);
            v.w = fmaxf(v.w, 0.f);
        }
        *(float4*)(crow + n) = v;
    }
}

// ---------------- launch ----------------
extern "C" void kernel_launch(void* const* d_in, const int* in_sizes, int n_in,
                              void* d_out, int out_size) {
    const int*   ids = (const int*)  d_in[0];
    const float* emb = (const float*)d_in[1];
    const float* w1  = (const float*)d_in[2];
    const float* b1  = (const float*)d_in[3];
    const float* w2  = (const float*)d_in[4];
    const float* b2  = (const float*)d_in[5];
    float*       out = (float*)d_out;

    k_reset<<<1, 1>>>();
    k_compact<<<NTOK / 256, 256>>>(ids);
    k_copy<<<NTOK, 256>>>(emb, ids, out);

    // ===== layer 1: H = relu(out[tok] @ W1 + b1), K=3200 =====
    {
        dim3 gs(HID / BN, SPLITS1);                       // 50 x 20 = 1000 blocks
        k_gs<1><<<gs, 128>>>(out, w1, HID, KCH1, DIM);
        dim3 gf((HID + 255) / 256, MAXM);
        k_fin<<<gf, 256>>>(b1, nullptr, HID, SPLITS1, 1, 0, HID);
        // fallback for rows >= 64 (early-exits when count <= 64)
        dim3 gb(HID / FBN, (NTOK - MAXM) / FBM);
        k_gemm<1, 1, 0><<<gb, 256>>>(out, w1, b1, nullptr, HID, DIM, DIM, HID);
    }

    // ===== layer 2: out[tok] = H @ W2 + b2, K=6400 =====
    {
        dim3 gs(DIM / BN, SPLITS2);                       // 25 x 40 = 1000 blocks
        k_gs<0><<<gs, 128>>>(nullptr, w2, DIM, KCH2, HID);
        dim3 gf((DIM + 255) / 256, MAXM);
        k_fin<<<gf, 256>>>(b2, out, DIM, SPLITS2, 0, 1, DIM);
        dim3 gb(DIM / FBN, (NTOK - MAXM) / FBM);
        k_gemm<0, 0, 1><<<gb, 256>>>(nullptr, w2, b2, out, DIM, HID, HID, DIM);
    }
}

// round 7
// speedup vs baseline: 1.6807x; 1.2626x over previous
#include <cuda_runtime.h>
#include <stdint.h>

#define DIM        3200
#define HID        6400
#define NTOK       16384   // 8 * 2048
#define NEW_START  32000

#define MAXM       64      // fast path covers rows [0, 64)
#define BN         64      // n per block
#define BK         32      // k per stage
#define SPLITS1    10      // layer1: K=3200 -> 320 per split (10 stages)
#define SPLITS2    20      // layer2: K=6400 -> 320 per split (10 stages)
#define KCHUNK     320

// smem strides (floats) chosen for conflict-free mma fragment loads
#define AS_LD      36      // As[64][36]
#define BS_LD      72      // Bs[32][72]

// fallback tiling (rows >= 64; early-exits normally)
#define FBM 64
#define FBN 64
#define FBK 16
#define FTM 4
#define FTN 4

// ---------------- scratch (static device globals; no allocation) ----------------
__device__ int   g_count;
__device__ int   g_tok[NTOK];
__device__ float g_H[(size_t)NTOK * HID];            // hidden activations
__device__ float g_P[(size_t)4096000];               // split-K partials (20*64*3200 = 10*64*6400)

// ---------------- helpers ----------------
__device__ __forceinline__ uint32_t cvt_tf32(float x) {
    uint32_t r;
    asm("cvt.rna.tf32.f32 %0, %1;" : "=r"(r) : "f"(x));
    return r;
}
__device__ __forceinline__ void mma_tf32(float* c, const uint32_t* a, const uint32_t* b) {
    asm volatile(
        "mma.sync.aligned.m16n8k8.row.col.f32.tf32.tf32.f32 "
        "{%0,%1,%2,%3}, {%4,%5,%6,%7}, {%8,%9}, {%0,%1,%2,%3};"
        : "+f"(c[0]), "+f"(c[1]), "+f"(c[2]), "+f"(c[3])
        : "r"(a[0]), "r"(a[1]), "r"(a[2]), "r"(a[3]), "r"(b[0]), "r"(b[1]));
}

// ---------------- kernel 0/1: reset + compact ----------------
__global__ void k_reset() { g_count = 0; }

__global__ void k_compact(const int* __restrict__ ids) {
    int t = blockIdx.x * blockDim.x + threadIdx.x;
    if (t < NTOK && ids[t] >= NEW_START) {
        int p = atomicAdd(&g_count, 1);
        g_tok[p] = t;
    }
}

// ---------------- kernel 2: embedding copy (all tokens) ----------------
__global__ void k_copy(const float* __restrict__ emb,
                       const int*   __restrict__ ids,
                       float*       __restrict__ out) {
    int t = blockIdx.x;
    const float4* src = (const float4*)(emb + (size_t)ids[t] * DIM);
    float4*       dst = (float4*)(out + (size_t)t * DIM);
    #pragma unroll 4
    for (int i = threadIdx.x; i < DIM / 4; i += blockDim.x)
        dst[i] = src[i];
}

// ---------------- TF32 mma.sync split-K GEMM ----------------
// grid: (N/64, splits), block 128 (4 warps in 2x2: warp = 32m x 32n).
// Partials -> g_P[(split*64 + m)*N + n0 + n]. Unique writer -> deterministic.
// GATHER_A=1: A row m = A + g_tok[m]*lda ; GATHER_A=0: A row m = g_H + m*lda
template<int GATHER_A>
__global__ void __launch_bounds__(128, 4)
k_mma(const float* __restrict__ A,
      const float* __restrict__ B,     // weights [K, N] row-major
      int N, int lda) {
    __shared__ uint32_t As[MAXM * AS_LD];   // tf32 bits, [m][k] stride 36
    __shared__ uint32_t Bs[BK * BS_LD];     // tf32 bits, [k][n] stride 72

    const int count = g_count;
    const int n0 = blockIdx.x * BN;
    const int kbase = blockIdx.y * KCHUNK;

    const int tid = threadIdx.x;      // 128
    const int wid = tid >> 5;
    const int lid = tid & 31;
    const int wm = wid >> 1;          // 0/1 : m-half
    const int wn = wid & 1;           // 0/1 : n-half
    const int fr = lid >> 2;          // 0..7
    const int fc = lid & 3;           // 0..3

    // A loader: row am = tid>>1, k-offset ah = (tid&1)*16 (16 floats)
    const int am = tid >> 1;
    const int ah = (tid & 1) * 16;
    const float* arow = nullptr;
    if (am < count) {
        if (GATHER_A) arow = A   + (size_t)g_tok[am] * lda;
        else          arow = g_H + (size_t)am        * lda;
    }

    // B loader: row bk = tid>>2 (0..31), col base bc = (tid&3)*16 (16 floats)
    const int bk = tid >> 2;
    const int bc = (tid & 3) * 16;

    float acc[2][4][4];
    #pragma unroll
    for (int mi = 0; mi < 2; mi++)
        #pragma unroll
        for (int ni = 0; ni < 4; ni++)
            #pragma unroll
            for (int j = 0; j < 4; j++) acc[mi][ni][j] = 0.0f;

    for (int s = 0; s < KCHUNK / BK; s++) {
        const int k0 = kbase + s * BK;

        // prefetch to regs
        float4 av[4];
        #pragma unroll
        for (int j = 0; j < 4; j++) av[j] = make_float4(0.f, 0.f, 0.f, 0.f);
        if (arow) {
            #pragma unroll
            for (int j = 0; j < 4; j++)
                av[j] = *(const float4*)(arow + k0 + ah + j * 4);
        }
        float4 bv[4];
        {
            const float* bsrc = B + (size_t)(k0 + bk) * N + n0 + bc;
            #pragma unroll
            for (int j = 0; j < 4; j++)
                bv[j] = *(const float4*)(bsrc + j * 4);
        }

        __syncthreads();   // previous stage fully consumed

        // STS (tf32-converted)
        #pragma unroll
        for (int j = 0; j < 4; j++) {
            uint32_t* d = &As[am * AS_LD + ah + j * 4];
            d[0] = cvt_tf32(av[j].x); d[1] = cvt_tf32(av[j].y);
            d[2] = cvt_tf32(av[j].z); d[3] = cvt_tf32(av[j].w);
        }
        #pragma unroll
        for (int j = 0; j < 4; j++) {
            uint32_t* d = &Bs[bk * BS_LD + bc + j * 4];
            d[0] = cvt_tf32(bv[j].x); d[1] = cvt_tf32(bv[j].y);
            d[2] = cvt_tf32(bv[j].z); d[3] = cvt_tf32(bv[j].w);
        }

        __syncthreads();   // tiles ready

        #pragma unroll
        for (int kk = 0; kk < BK; kk += 8) {
            uint32_t a[2][4];
            #pragma unroll
            for (int mi = 0; mi < 2; mi++) {
                const int m0 = wm * 32 + mi * 16;
                a[mi][0] = As[(m0 + fr)     * AS_LD + kk + fc];
                a[mi][1] = As[(m0 + fr + 8) * AS_LD + kk + fc];
                a[mi][2] = As[(m0 + fr)     * AS_LD + kk + fc + 4];
                a[mi][3] = As[(m0 + fr + 8) * AS_LD + kk + fc + 4];
            }
            uint32_t b[4][2];
            #pragma unroll
            for (int ni = 0; ni < 4; ni++) {
                const int n = wn * 32 + ni * 8 + fr;
                b[ni][0] = Bs[(kk + fc)     * BS_LD + n];
                b[ni][1] = Bs[(kk + fc + 4) * BS_LD + n];
            }
            #pragma unroll
            for (int mi = 0; mi < 2; mi++)
                #pragma unroll
                for (int ni = 0; ni < 4; ni++)
                    mma_tf32(acc[mi][ni], a[mi], b[ni]);
        }
    }

    // write partials (rows >= count hold zeros from zero A rows; finalize ignores them)
    float* pbase = g_P + (size_t)blockIdx.y * MAXM * N + n0;
    #pragma unroll
    for (int mi = 0; mi < 2; mi++) {
        const int row = wm * 32 + mi * 16 + fr;
        #pragma unroll
        for (int ni = 0; ni < 4; ni++) {
            const int col = wn * 32 + ni * 8 + 2 * fc;
            float* p0 = pbase + (size_t)row * N + col;
            p0[0] = acc[mi][ni][0];
            p0[1] = acc[mi][ni][1];
            float* p1 = pbase + (size_t)(row + 8) * N + col;
            p1[0] = acc[mi][ni][2];
            p1[1] = acc[mi][ni][3];
        }
    }
}

// ---------------- finalize: reduce splits + bias (+relu) + write ----------------
__global__ void k_fin(const float* __restrict__ bias,
                      float*       __restrict__ dst,    // used when scatter==1
                      int N, int splits, int relu, int scatter, int ldc) {
    const int n = blockIdx.x * 256 + threadIdx.x;
    const int m = blockIdx.y;
    const int count = g_count;
    if (n >= N || m >= count) return;
    float s = bias[n];
    for (int i = 0; i < splits; i++)
        s += g_P[((size_t)i * MAXM + m) * N + n];
    if (relu) s = fmaxf(s, 0.f);
    if (scatter) dst[(size_t)g_tok[m] * ldc + n] = s;
    else         g_H[(size_t)m * ldc + n] = s;
}

// ---------------- fallback full-K GEMM (rows >= 64; early-exits normally) --------
template<int RELU, int GATHER_A, int SCATTER_C>
__global__ void k_gemm(const float* __restrict__ A,
                       const float* __restrict__ B,
                       const float* __restrict__ bias,
                       float*       __restrict__ C,
                       int N, int K, int lda, int ldc) {
    __shared__ float As[FBK][FBM + 1];
    __shared__ float Bs[FBK][FBN];

    const int count = g_count;
    const int m0 = MAXM + blockIdx.y * FBM;
    if (m0 >= count) return;
    const int n0 = blockIdx.x * FBN;

    const int tid = threadIdx.x;
    const int tx = tid & 15;
    const int ty = tid >> 4;

    const int a_mi = tid >> 2;
    const int a_k  = (tid & 3) * 4;
    const int a_m  = m0 + a_mi;
    const float* arow = nullptr;
    if (a_m < count) {
        if (GATHER_A) arow = A + (size_t)g_tok[a_m] * lda;
        else          arow = g_H + (size_t)a_m * lda;
    }

    const int b_kb = tid >> 4;
    const int b_n  = (tid & 15) * 4;

    float acc[FTM][FTN];
    #pragma unroll
    for (int i = 0; i < FTM; i++)
        #pragma unroll
        for (int j = 0; j < FTN; j++) acc[i][j] = 0.0f;

    for (int k0 = 0; k0 < K; k0 += FBK) {
        float4 va = make_float4(0.f, 0.f, 0.f, 0.f);
        if (arow) va = *(const float4*)(arow + k0 + a_k);
        As[a_k + 0][a_mi] = va.x;
        As[a_k + 1][a_mi] = va.y;
        As[a_k + 2][a_mi] = va.z;
        As[a_k + 3][a_mi] = va.w;

        float4 vb = *(const float4*)(B + (size_t)(k0 + b_kb) * N + n0 + b_n);
        *(float4*)&Bs[b_kb][b_n] = vb;

        __syncthreads();

        #pragma unroll
        for (int kk = 0; kk < FBK; kk++) {
            float a[FTM], b[FTN];
            #pragma unroll
            for (int i = 0; i < FTM; i++) a[i] = As[kk][ty * FTM + i];
            #pragma unroll
            for (int j = 0; j < FTN; j++) b[j] = Bs[kk][tx * FTN + j];
            #pragma unroll
            for (int i = 0; i < FTM; i++)
                #pragma unroll
                for (int j = 0; j < FTN; j++)
                    acc[i][j] = fmaf(a[i], b[j], acc[i][j]);
        }
        __syncthreads();
    }

    const int n = n0 + tx * FTN;
    float4 bv = *(const float4*)(bias + n);
    #pragma unroll
    for (int i = 0; i < FTM; i++) {
        int m = m0 + ty * FTM + i;
        if (m >= count) continue;
        float* crow;
        if (SCATTER_C) crow = C + (size_t)g_tok[m] * ldc;
        else           crow = g_H + (size_t)m * ldc;
        float4 v;
        v.x = acc[i][0] + bv.x;
        v.y = acc[i][1] + bv.y;
        v.z = acc[i][2] + bv.z;
        v.w = acc[i][3] + bv.w;
        if (RELU) {
            v.x = fmaxf(v.x, 0.f);
            v.y = fmaxf(v.y, 0.f);
            v.z = fmaxf(v.z, 0.f);
            v.w = fmaxf(v.w, 0.f);
        }
        *(float4*)(crow + n) = v;
    }
}

// ---------------- launch ----------------
extern "C" void kernel_launch(void* const* d_in, const int* in_sizes, int n_in,
                              void* d_out, int out_size) {
    const int*   ids = (const int*)  d_in[0];
    const float* emb = (const float*)d_in[1];
    const float* w1  = (const float*)d_in[2];
    const float* b1  = (const float*)d_in[3];
    const float* w2  = (const float*)d_in[4];
    const float* b2  = (const float*)d_in[5];
    float*       out = (float*)d_out;

    k_reset<<<1, 1>>>();
    k_compact<<<NTOK / 256, 256>>>(ids);
    k_copy<<<NTOK, 256>>>(emb, ids, out);

    // ===== layer 1: H = relu(out[tok] @ W1 + b1), K=3200 =====
    {
        dim3 gs(HID / BN, SPLITS1);                      // 100 x 10 = 1000 blocks
        k_mma<1><<<gs, 128>>>(out, w1, HID, DIM);
        dim3 gf((HID + 255) / 256, MAXM);
        k_fin<<<gf, 256>>>(b1, nullptr, HID, SPLITS1, 1, 0, HID);
        dim3 gb(HID / FBN, (NTOK - MAXM) / FBM);
        k_gemm<1, 1, 0><<<gb, 256>>>(out, w1, b1, nullptr, HID, DIM, DIM, HID);
    }

    // ===== layer 2: out[tok] = H @ W2 + b2, K=6400 =====
    {
        dim3 gs(DIM / BN, SPLITS2);                      // 50 x 20 = 1000 blocks
        k_mma<0><<<gs, 128>>>(nullptr, w2, DIM, HID);
        dim3 gf((DIM + 255) / 256, MAXM);
        k_fin<<<gf, 256>>>(b2, out, DIM, SPLITS2, 0, 1, DIM);
        dim3 gb(DIM / FBN, (NTOK - MAXM) / FBM);
        k_gemm<0, 0, 1><<<gb, 256>>>(nullptr, w2, b2, out, DIM, HID, HID, DIM);
    }
}

// round 9
// speedup vs baseline: 1.8511x; 1.1014x over previous
#include <cuda_runtime.h>
#include <stdint.h>

#define DIM        3200
#define HID        6400
#define NTOK       16384   // 8 * 2048
#define NEW_START  32000

#define MAXM       64      // fast path covers rows [0, 64)
#define BN         128     // n per block
#define BK         32      // k per stage
#define KCHUNK     160     // k per split (5 stages)
#define SPLITS1    20      // layer1: K=3200
#define SPLITS2    40      // layer2: K=6400

// smem: 3-stage ring; per stage A[64][36] f32 (9216B) + B[32][136] f32 (17408B)
#define AS_LD      36
#define BS_LD      136     // 128 + 8 pad; 136 % 32 == 8 -> conflict-free frag reads
#define A_BYTES    9216
#define B_ROW_B    (BS_LD * 4)          // 544
#define STAGE_B    (A_BYTES + BK * B_ROW_B)   // 9216 + 17408 = 26624
#define SMEM_B     (3 * STAGE_B)        // 79872

// fallback tiling (rows >= 64; early-exits normally)
#define FBM 64
#define FBN 64
#define FBK 16
#define FTM 4
#define FTN 4

// ---------------- scratch (static device globals; no allocation) ----------------
__device__ int   g_count;
__device__ int   g_tok[NTOK];
__device__ float g_H[(size_t)NTOK * HID];            // hidden activations
__device__ float g_P[(size_t)8192000];               // split-K partials (20*64*6400 = 40*64*3200)

// ---------------- helpers ----------------
__device__ __forceinline__ uint32_t smem_u32(const void* p) {
    uint32_t a;
    asm("{ .reg .u64 t; cvta.to.shared.u64 t, %1; cvt.u32.u64 %0, t; }" : "=r"(a) : "l"(p));
    return a;
}
__device__ __forceinline__ void cp16(uint32_t dst, const void* src, int srcsz) {
    asm volatile("cp.async.ca.shared.global [%0], [%1], 16, %2;"
                 :: "r"(dst), "l"(__cvta_generic_to_global(src)), "r"(srcsz) : "memory");
}
#define CP_COMMIT() asm volatile("cp.async.commit_group;" ::: "memory")
#define CP_WAIT2()  asm volatile("cp.async.wait_group 2;" ::: "memory")

__device__ __forceinline__ void mma_tf32(float* c, const uint32_t* a, const uint32_t* b) {
    asm volatile(
        "mma.sync.aligned.m16n8k8.row.col.f32.tf32.tf32.f32 "
        "{%0,%1,%2,%3}, {%4,%5,%6,%7}, {%8,%9}, {%0,%1,%2,%3};"
        : "+f"(c[0]), "+f"(c[1]), "+f"(c[2]), "+f"(c[3])
        : "r"(a[0]), "r"(a[1]), "r"(a[2]), "r"(a[3]), "r"(b[0]), "r"(b[1]));
}

// ---------------- kernel 0/1: reset + compact ----------------
__global__ void k_reset() { g_count = 0; }

__global__ void k_compact(const int* __restrict__ ids) {
    int t = blockIdx.x * blockDim.x + threadIdx.x;
    if (t < NTOK && ids[t] >= NEW_START) {
        int p = atomicAdd(&g_count, 1);
        g_tok[p] = t;
    }
}

// ---------------- kernel 2: embedding copy (all tokens) ----------------
__global__ void k_copy(const float* __restrict__ emb,
                       const int*   __restrict__ ids,
                       float*       __restrict__ out) {
    int t = blockIdx.x;
    const float4* src = (const float4*)(emb + (size_t)ids[t] * DIM);
    float4*       dst = (float4*)(out + (size_t)t * DIM);
    #pragma unroll 4
    for (int i = threadIdx.x; i < DIM / 4; i += blockDim.x)
        dst[i] = src[i];
}

// ---------------- TF32 mma.sync split-K GEMM, cp.async 3-stage pipeline ----------
// grid: (N/128, splits), block 256 (8 warps, 2m x 4n; warp = 32m x 32n).
// Partials -> g_P[(split*64 + m)*N + n0 + n]. Unique writer -> deterministic.
template<int GATHER_A>
__global__ void __launch_bounds__(256, 2)
k_mma(const float* __restrict__ A,
      const float* __restrict__ B,     // weights [K, N] row-major
      int N, int lda) {
    extern __shared__ char smbuf[];
    const uint32_t smb = smem_u32(smbuf);

    const int count = g_count;
    const int n0 = blockIdx.x * BN;
    const int kbase = blockIdx.y * KCHUNK;
    const int nstage = KCHUNK / BK;   // 5

    const int tid = threadIdx.x;      // 256
    const int wid = tid >> 5;
    const int lid = tid & 31;
    const int wm = wid >> 2;          // 0/1
    const int wn = wid & 3;           // 0..3
    const int fr = lid >> 2;          // 0..7
    const int fc = lid & 3;           // 0..3

    // ---- A chunk assignment: 512 chunks of 16B (m = c>>3, kq = c&7); 2 per thread
    int am[2]  = { tid >> 3, (tid + 256) >> 3 };
    int akq[2] = { tid & 7,  (tid + 256) & 7 };
    const float* asrc[2];
    int asz[2];
    uint32_t adst[2];
    #pragma unroll
    for (int i = 0; i < 2; i++) {
        asz[i] = 0;
        asrc[i] = B;                  // dummy valid address (unused when srcsz=0)
        if (am[i] < count) {
            const float* base = GATHER_A ? A : g_H;
            int row = GATHER_A ? g_tok[am[i]] : am[i];
            asrc[i] = base + (size_t)row * lda + akq[i] * 4;
            asz[i] = 16;
        }
        adst[i] = smb + am[i] * (AS_LD * 4) + akq[i] * 16;
    }

    // ---- B chunk assignment: 1024 chunks (bk = c>>5, nc = c&31); 4 per thread
    const float* bsrc[4];
    uint32_t bdst[4];
    #pragma unroll
    for (int j = 0; j < 4; j++) {
        int c = tid + 256 * j;
        int bk = c >> 5, nc = c & 31;
        bsrc[j] = B + (size_t)bk * N + n0 + nc * 4;
        bdst[j] = smb + A_BYTES + bk * B_ROW_B + nc * 16;
    }

    float acc[2][4][4];
    #pragma unroll
    for (int mi = 0; mi < 2; mi++)
        #pragma unroll
        for (int ni = 0; ni < 4; ni++)
            #pragma unroll
            for (int j = 0; j < 4; j++) acc[mi][ni][j] = 0.0f;

    // stage issue
    auto issue = [&](int st) {
        const int off = (st % 3) * STAGE_B;
        const int k0 = kbase + st * BK;
        cp16(adst[0] + off, asrc[0] + k0, asz[0]);
        cp16(adst[1] + off, asrc[1] + k0, asz[1]);
        #pragma unroll
        for (int j = 0; j < 4; j++)
            cp16(bdst[j] + off, bsrc[j] + (size_t)k0 * N, 16);
    };

    issue(0); CP_COMMIT();
    issue(1); CP_COMMIT();

    for (int s = 0; s < nstage; s++) {
        if (s + 2 < nstage) issue(s + 2);
        CP_COMMIT();
        CP_WAIT2();            // stage s complete; s+1, s+2 in flight
        __syncthreads();

        const uint32_t* As = (const uint32_t*)(smbuf + (s % 3) * STAGE_B);
        const uint32_t* Bs = (const uint32_t*)(smbuf + (s % 3) * STAGE_B + A_BYTES);

        #pragma unroll
        for (int kk = 0; kk < BK; kk += 8) {
            uint32_t a[2][4];
            #pragma unroll
            for (int mi = 0; mi < 2; mi++) {
                const int m0 = wm * 32 + mi * 16;
                a[mi][0] = As[(m0 + fr)     * AS_LD + kk + fc];
                a[mi][1] = As[(m0 + fr + 8) * AS_LD + kk + fc];
                a[mi][2] = As[(m0 + fr)     * AS_LD + kk + fc + 4];
                a[mi][3] = As[(m0 + fr + 8) * AS_LD + kk + fc + 4];
            }
            uint32_t b[4][2];
            #pragma unroll
            for (int ni = 0; ni < 4; ni++) {
                const int n = wn * 32 + ni * 8 + fr;
                b[ni][0] = Bs[(kk + fc)     * BS_LD + n];
                b[ni][1] = Bs[(kk + fc + 4) * BS_LD + n];
            }
            #pragma unroll
            for (int mi = 0; mi < 2; mi++)
                #pragma unroll
                for (int ni = 0; ni < 4; ni++)
                    mma_tf32(acc[mi][ni], a[mi], b[ni]);
        }
        __syncthreads();       // buffer free before next issue overwrites it
    }

    // write partials
    float* pbase = g_P + (size_t)blockIdx.y * MAXM * N + n0;
    #pragma unroll
    for (int mi = 0; mi < 2; mi++) {
        const int row = wm * 32 + mi * 16 + fr;
        #pragma unroll
        for (int ni = 0; ni < 4; ni++) {
            const int col = wn * 32 + ni * 8 + 2 * fc;
            float* p0 = pbase + (size_t)row * N + col;
            p0[0] = acc[mi][ni][0];
            p0[1] = acc[mi][ni][1];
            float* p1 = pbase + (size_t)(row + 8) * N + col;
            p1[0] = acc[mi][ni][2];
            p1[1] = acc[mi][ni][3];
        }
    }
}

// ---------------- finalize: reduce splits + bias (+relu) + write ----------------
__global__ void k_fin(const float* __restrict__ bias,
                      float*       __restrict__ dst,    // used when scatter==1
                      int N, int splits, int relu, int scatter, int ldc) {
    const int n = blockIdx.x * 256 + threadIdx.x;
    const int m = blockIdx.y;
    const int count = g_count;
    if (n >= N || m >= count) return;
    float s = bias[n];
    for (int i = 0; i < splits; i++)
        s += g_P[((size_t)i * MAXM + m) * N + n];
    if (relu) s = fmaxf(s, 0.f);
    if (scatter) dst[(size_t)g_tok[m] * ldc + n] = s;
    else         g_H[(size_t)m * ldc + n] = s;
}

// ---------------- fallback full-K GEMM (rows >= 64; early-exits normally) --------
template<int RELU, int GATHER_A, int SCATTER_C>
__global__ void k_gemm(const float* __restrict__ A,
                       const float* __restrict__ B,
                       const float* __restrict__ bias,
                       float*       __restrict__ C,
                       int N, int K, int lda, int ldc) {
    __shared__ float As[FBK][FBM + 1];
    __shared__ float Bs[FBK][FBN];

    const int count = g_count;
    const int m0 = MAXM + blockIdx.y * FBM;
    if (m0 >= count) return;
    const int n0 = blockIdx.x * FBN;

    const int tid = threadIdx.x;
    const int tx = tid & 15;
    const int ty = tid >> 4;

    const int a_mi = tid >> 2;
    const int a_k  = (tid & 3) * 4;
    const int a_m  = m0 + a_mi;
    const float* arow = nullptr;
    if (a_m < count) {
        if (GATHER_A) arow = A + (size_t)g_tok[a_m] * lda;
        else          arow = g_H + (size_t)a_m * lda;
    }

    const int b_kb = tid >> 4;
    const int b_n  = (tid & 15) * 4;

    float acc[FTM][FTN];
    #pragma unroll
    for (int i = 0; i < FTM; i++)
        #pragma unroll
        for (int j = 0; j < FTN; j++) acc[i][j] = 0.0f;

    for (int k0 = 0; k0 < K; k0 += FBK) {
        float4 va = make_float4(0.f, 0.f, 0.f, 0.f);
        if (arow) va = *(const float4*)(arow + k0 + a_k);
        As[a_k + 0][a_mi] = va.x;
        As[a_k + 1][a_mi] = va.y;
        As[a_k + 2][a_mi] = va.z;
        As[a_k + 3][a_mi] = va.w;

        float4 vb = *(const float4*)(B + (size_t)(k0 + b_kb) * N + n0 + b_n);
        *(float4*)&Bs[b_kb][b_n] = vb;

        __syncthreads();

        #pragma unroll
        for (int kk = 0; kk < FBK; kk++) {
            float a[FTM], b[FTN];
            #pragma unroll
            for (int i = 0; i < FTM; i++) a[i] = As[kk][ty * FTM + i];
            #pragma unroll
            for (int j = 0; j < FTN; j++) b[j] = Bs[kk][tx * FTN + j];
            #pragma unroll
            for (int i = 0; i < FTM; i++)
                #pragma unroll
                for (int j = 0; j < FTN; j++)
                    acc[i][j] = fmaf(a[i], b[j], acc[i][j]);
        }
        __syncthreads();
    }

    const int n = n0 + tx * FTN;
    float4 bv = *(const float4*)(bias + n);
    #pragma unroll
    for (int i = 0; i < FTM; i++) {
        int m = m0 + ty * FTM + i;
        if (m >= count) continue;
        float* crow;
        if (SCATTER_C) crow = C + (size_t)g_tok[m] * ldc;
        else           crow = g_H + (size_t)m * ldc;
        float4 v;
        v.x = acc[i][0] + bv.x;
        v.y = acc[i][1] + bv.y;
        v.z = acc[i][2] + bv.z;
        v.w = acc[i][3] + bv.w;
        if (RELU) {
            v.x = fmaxf(v.x, 0.f);
            v.y = fmaxf(v.y, 0.f);
            v.z = fmaxf(v.z, 0.f);
            v.w = fmaxf(v.w, 0.f);
        }
        *(float4*)(crow + n) = v;
    }
}

// ---------------- launch ----------------
extern "C" void kernel_launch(void* const* d_in, const int* in_sizes, int n_in,
                              void* d_out, int out_size) {
    const int*   ids = (const int*)  d_in[0];
    const float* emb = (const float*)d_in[1];
    const float* w1  = (const float*)d_in[2];
    const float* b1  = (const float*)d_in[3];
    const float* w2  = (const float*)d_in[4];
    const float* b2  = (const float*)d_in[5];
    float*       out = (float*)d_out;

    cudaFuncSetAttribute(k_mma<1>, cudaFuncAttributeMaxDynamicSharedMemorySize, SMEM_B);
    cudaFuncSetAttribute(k_mma<0>, cudaFuncAttributeMaxDynamicSharedMemorySize, SMEM_B);

    k_reset<<<1, 1>>>();
    k_compact<<<NTOK / 256, 256>>>(ids);
    k_copy<<<NTOK, 256>>>(emb, ids, out);

    // ===== layer 1: H = relu(out[tok] @ W1 + b1), K=3200 =====
    {
        dim3 gs(HID / BN, SPLITS1);                      // 50 x 20 = 1000 blocks
        k_mma<1><<<gs, 256, SMEM_B>>>(out, w1, HID, DIM);
        dim3 gf((HID + 255) / 256, MAXM);
        k_fin<<<gf, 256>>>(b1, nullptr, HID, SPLITS1, 1, 0, HID);
        dim3 gb(HID / FBN, (NTOK - MAXM) / FBM);
        k_gemm<1, 1, 0><<<gb, 256>>>(out, w1, b1, nullptr, HID, DIM, DIM, HID);
    }

    // ===== layer 2: out[tok] = H @ W2 + b2, K=6400 =====
    {
        dim3 gs(DIM / BN, SPLITS2);                      // 25 x 40 = 1000 blocks
        k_mma<0><<<gs, 256, SMEM_B>>>(nullptr, w2, DIM, HID);
        dim3 gf((DIM + 255) / 256, MAXM);
        k_fin<<<gf, 256>>>(b2, out, DIM, SPLITS2, 0, 1, DIM);
        dim3 gb(DIM / FBN, (NTOK - MAXM) / FBM);
        k_gemm<0, 0, 1><<<gb, 256>>>(nullptr, w2, b2, out, DIM, HID, HID, DIM);
    }
}